// round 1
// baseline (speedup 1.0000x reference)
#include <cuda_runtime.h>
#include <cuda_bf16.h>
#include <cstdint>

// ---------------- problem constants ----------------
static constexpr int N_  = 16;
static constexpr int C_  = 256;
static constexpr int H_  = 56;
static constexpr int W_  = 56;
static constexpr int K_  = 256;
static constexpr int HW  = H_ * W_;          // 3136
static constexpr int CHW = C_ * HW;          // 802816
static constexpr long long NE_X = (long long)N_ * CHW;   // 12,845,056
static constexpr int NE_W = K_ * C_ * 9;     // 589,824
static constexpr int NG_X = (int)((NE_X + 35) / 36);     // 356,808
static constexpr int NG_W = NE_W / 36;       // 16,384 (exact)
static constexpr int MGEMM = N_ * HW;        // 50,176 = 392*128

// ---------------- device scratch (no allocs allowed) ----------------
__device__ __nv_bfloat16 g_xq_nchw[12845056];
__device__ __nv_bfloat16 g_xq[12845056];        // NHWC: ((n*56+h)*56+w)*256 + c
__device__ __nv_bfloat16 g_wt[9 * 256 * 256];   // [rs][kout][c]

// ---------------- BFP quantization helper ----------------
// Replicates: e = floor(log2(maxabs)); scale = 2^(e-7); q = clip(rint(v/scale), -128, 127)*scale
__device__ __forceinline__ float bfp_apply(float v, float inv, float scale) {
    float r = rintf(v * inv);                 // rintf = round-half-even (matches jnp.round)
    r = fminf(fmaxf(r, -128.0f), 127.0f);
    return r * scale;
}

// ---------------- quantize x (flat NCHW groups of 36) ----------------
__global__ void quant_x_kernel(const float* __restrict__ x) {
    int g = blockIdx.x * (blockDim.x >> 5) + (threadIdx.x >> 5);
    if (g >= NG_X) return;
    int lane = threadIdx.x & 31;
    long long base = (long long)g * 36;
    long long i1 = base + lane;
    long long i2 = base + 32 + lane;
    bool ok1 = (i1 < NE_X);
    bool ok2 = (lane < 4) && (i2 < NE_X);
    float v1 = ok1 ? x[i1] : 0.0f;
    float v2 = ok2 ? x[i2] : 0.0f;
    float m = fmaxf(fabsf(v1), fabsf(v2));
    #pragma unroll
    for (int o = 16; o > 0; o >>= 1)
        m = fmaxf(m, __shfl_xor_sync(0xffffffffu, m, o));
    if (m > 0.0f) {
        int e;
        frexpf(m, &e);                        // maxabs = f*2^e, f in [0.5,1) -> floor(log2)=e-1
        float scale = ldexpf(1.0f, e - 8);    // 2^((e-1)-7)
        float inv   = ldexpf(1.0f, 8 - e);
        v1 = bfp_apply(v1, inv, scale);
        v2 = bfp_apply(v2, inv, scale);
    } else {
        v1 = 0.0f; v2 = 0.0f;
    }
    if (ok1) g_xq_nchw[i1] = __float2bfloat16(v1);   // exact: int8 * 2^k fits bf16
    if (ok2) g_xq_nchw[i2] = __float2bfloat16(v2);
}

// ---------------- transpose xq: NCHW -> NHWC ----------------
__global__ void transpose_x_kernel() {
    __shared__ __nv_bfloat16 t[32][33];
    int n   = blockIdx.z;
    int hw0 = blockIdx.y * 32;     // 3136/32 = 98
    int c0  = blockIdx.x * 32;     // 256/32 = 8
    int tx = threadIdx.x & 31;
    int ty = threadIdx.x >> 5;     // 0..7
    const __nv_bfloat16* src = g_xq_nchw + (long long)n * CHW;
    #pragma unroll
    for (int i = 0; i < 4; ++i) {
        int c = c0 + ty + i * 8;
        t[ty + i * 8][tx] = src[(long long)c * HW + hw0 + tx];
    }
    __syncthreads();
    __nv_bfloat16* dst = g_xq + (long long)n * CHW;
    #pragma unroll
    for (int i = 0; i < 4; ++i) {
        int hw = hw0 + ty + i * 8;
        dst[(long long)hw * C_ + c0 + tx] = t[tx][ty + i * 8];
    }
}

// ---------------- quantize w (flat OIHW groups of 36) + relayout [rs][kout][c] ----------------
__device__ __forceinline__ void store_w(int f, float q) {
    int kout = f / 2304;
    int rem  = f - kout * 2304;
    int c    = rem / 9;
    int rs   = rem - c * 9;
    g_wt[(rs * K_ + kout) * C_ + c] = __float2bfloat16(q);
}

__global__ void quant_w_kernel(const float* __restrict__ w) {
    int g = blockIdx.x * (blockDim.x >> 5) + (threadIdx.x >> 5);
    if (g >= NG_W) return;
    int lane = threadIdx.x & 31;
    int base = g * 36;
    int i1 = base + lane;
    int i2 = base + 32 + lane;
    float v1 = w[i1];
    float v2 = (lane < 4) ? w[i2] : 0.0f;
    float m = fmaxf(fabsf(v1), fabsf(v2));
    #pragma unroll
    for (int o = 16; o > 0; o >>= 1)
        m = fmaxf(m, __shfl_xor_sync(0xffffffffu, m, o));
    if (m > 0.0f) {
        int e;
        frexpf(m, &e);
        float scale = ldexpf(1.0f, e - 8);
        float inv   = ldexpf(1.0f, 8 - e);
        v1 = bfp_apply(v1, inv, scale);
        v2 = bfp_apply(v2, inv, scale);
    } else {
        v1 = 0.0f; v2 = 0.0f;
    }
    store_w(i1, v1);
    if (lane < 4) store_w(i2, v2);
}

// ---------------- bf16 HMMA implicit-GEMM conv ----------------
__device__ __forceinline__ void mma16816(float* d, const uint32_t* a, const uint32_t* b) {
    asm volatile(
        "mma.sync.aligned.m16n8k16.row.col.f32.bf16.bf16.f32 "
        "{%0,%1,%2,%3}, {%4,%5,%6,%7}, {%8,%9}, {%0,%1,%2,%3};\n"
        : "+f"(d[0]), "+f"(d[1]), "+f"(d[2]), "+f"(d[3])
        : "r"(a[0]), "r"(a[1]), "r"(a[2]), "r"(a[3]),
          "r"(b[0]), "r"(b[1]));
}

__global__ void __launch_bounds__(256, 2)
conv_kernel(const float* __restrict__ bias, float* __restrict__ out) {
    constexpr int PITCH = 40;   // halves per smem row: 20 words/row -> conflict-free frag LDS
    __shared__ __align__(16) __nv_bfloat16 As[128 * PITCH];
    __shared__ __align__(16) __nv_bfloat16 Bs[128 * PITCH];
    __shared__ int s_n[128], s_pix[128];

    int tid = threadIdx.x;
    int m0  = blockIdx.y * 128;      // 0..391 tiles of M
    int bn  = blockIdx.x;            // 0..1 tiles of N(=K_out)

    if (tid < 128) {
        int m  = m0 + tid;
        int nn = m / HW;
        s_n[tid]   = nn;
        s_pix[tid] = m - nn * HW;
    }

    // per-thread A/B load metadata: each thread owns rows (tid>>4)+16*i, cpair tid&15
    int lsub  = tid & 15;            // c-pair index (2 halves = 4B)
    int lrow0 = tid >> 4;            // 0..15
    int am[8];                       // flat pixel index m (== NHWC pixel index)
    int ap[8], aq[8];
    #pragma unroll
    for (int i = 0; i < 8; ++i) {
        int m  = m0 + lrow0 + i * 16;
        int nn = m / HW;
        int rem = m - nn * HW;
        int p = rem / W_;
        ap[i] = p;
        aq[i] = rem - p * W_;
        am[i] = m;
    }
    __syncthreads();

    int warp = tid >> 5, lane = tid & 31;
    int wm = warp & 1;               // 2 warps along M (64 rows each)
    int wn = warp >> 1;              // 4 warps along N (32 cols each)
    int gi = lane >> 2, ti = lane & 3;

    float acc[4][4][4];
    #pragma unroll
    for (int i = 0; i < 4; ++i)
        #pragma unroll
        for (int j = 0; j < 4; ++j)
            #pragma unroll
            for (int k = 0; k < 4; ++k) acc[i][j][k] = 0.0f;

    for (int cb = 0; cb < 8; ++cb) {             // channel chunks of 32
        int cbase = cb * 32;
        #pragma unroll
        for (int r = 0; r < 3; ++r) {
            #pragma unroll
            for (int s = 0; s < 3; ++s) {
                int rs   = r * 3 + s;
                int doff = (r - 1) * 56 + (s - 1);   // pixel-index shift in NHWC
                // ---- load A tile (128 x 32 bf16), NHWC so c contiguous ----
                #pragma unroll
                for (int i = 0; i < 8; ++i) {
                    int h = ap[i] + r - 1;
                    int w = aq[i] + s - 1;
                    uint32_t v = 0u;
                    if ((unsigned)h < 56u && (unsigned)w < 56u) {
                        long long off = (long long)(am[i] + doff) * C_ + cbase + lsub * 2;
                        v = *(const uint32_t*)(g_xq + off);
                    }
                    *(uint32_t*)(As + (lrow0 + i * 16) * PITCH + lsub * 2) = v;
                }
                // ---- load B tile (128 kout x 32 c), g_wt[rs][kout][c] so c contiguous ----
                #pragma unroll
                for (int i = 0; i < 8; ++i) {
                    int kout = lrow0 + i * 16;
                    uint32_t v = *(const uint32_t*)(g_wt + ((rs * K_ + bn * 128 + kout) * C_ + cbase + lsub * 2));
                    *(uint32_t*)(Bs + kout * PITCH + lsub * 2) = v;
                }
                __syncthreads();
                // ---- 128x128x32 MMA ----
                #pragma unroll
                for (int kk = 0; kk < 32; kk += 16) {
                    uint32_t a[4][4], b[4][2];
                    #pragma unroll
                    for (int i = 0; i < 4; ++i) {
                        const __nv_bfloat16* pA = As + (wm * 64 + i * 16 + gi) * PITCH + kk + ti * 2;
                        a[i][0] = *(const uint32_t*)pA;
                        a[i][1] = *(const uint32_t*)(pA + 8 * PITCH);
                        a[i][2] = *(const uint32_t*)(pA + 8);
                        a[i][3] = *(const uint32_t*)(pA + 8 * PITCH + 8);
                    }
                    #pragma unroll
                    for (int j = 0; j < 4; ++j) {
                        const __nv_bfloat16* pB = Bs + (wn * 32 + j * 8 + gi) * PITCH + kk + ti * 2;
                        b[j][0] = *(const uint32_t*)pB;
                        b[j][1] = *(const uint32_t*)(pB + 8);
                    }
                    #pragma unroll
                    for (int i = 0; i < 4; ++i)
                        #pragma unroll
                        for (int j = 0; j < 4; ++j)
                            mma16816(acc[i][j], a[i], b[j]);
                }
                __syncthreads();
            }
        }
    }

    // ---- epilogue: out[(n*256 + kout)*3136 + pix] = acc + bias ----
    #pragma unroll
    for (int i = 0; i < 4; ++i) {
        int rl0 = wm * 64 + i * 16 + gi;
        int rl1 = rl0 + 8;
        int o0 = s_n[rl0] * CHW + s_pix[rl0];
        int o1 = s_n[rl1] * CHW + s_pix[rl1];
        #pragma unroll
        for (int j = 0; j < 4; ++j) {
            int kout = bn * 128 + wn * 32 + j * 8 + ti * 2;
            float b0 = bias[kout];
            float b1 = bias[kout + 1];
            out[o0 + kout * HW]        = acc[i][j][0] + b0;
            out[o0 + (kout + 1) * HW]  = acc[i][j][1] + b1;
            out[o1 + kout * HW]        = acc[i][j][2] + b0;
            out[o1 + (kout + 1) * HW]  = acc[i][j][3] + b1;
        }
    }
}

// ---------------- launch ----------------
extern "C" void kernel_launch(void* const* d_in, const int* in_sizes, int n_in,
                              void* d_out, int out_size) {
    const float* x    = (const float*)d_in[0];
    const float* w    = (const float*)d_in[1];
    const float* bias = (const float*)d_in[2];
    float* out = (float*)d_out;

    quant_x_kernel<<<(NG_X + 7) / 8, 256>>>(x);
    quant_w_kernel<<<(NG_W + 7) / 8, 256>>>(w);
    {
        dim3 g(8, 98, 16);
        transpose_x_kernel<<<g, 256>>>();
    }
    {
        dim3 g(2, MGEMM / 128);
        conv_kernel<<<g, 256>>>(bias, out);
    }
}

// round 2
// speedup vs baseline: 1.3737x; 1.3737x over previous
#include <cuda_runtime.h>
#include <cuda_bf16.h>
#include <cstdint>

// ---------------- problem constants ----------------
static constexpr int N_  = 16;
static constexpr int C_  = 256;
static constexpr int H_  = 56;
static constexpr int W_  = 56;
static constexpr int K_  = 256;
static constexpr int HW  = H_ * W_;          // 3136
static constexpr int CHW = C_ * HW;          // 802816
static constexpr long long NE_X = (long long)N_ * CHW;   // 12,845,056
static constexpr int NE_W = K_ * C_ * 9;     // 589,824
static constexpr int NG_X = (int)((NE_X + 35) / 36);     // 356,808
static constexpr int NG_W = NE_W / 36;       // 16,384 (exact)
static constexpr int MGEMM = N_ * HW;        // 50,176 = 392*128

// ---------------- device scratch (no allocs allowed) ----------------
__device__ __nv_bfloat16 g_xq_nchw[12845056];
__device__ __nv_bfloat16 g_xq[12845056];        // NHWC: ((n*56+h)*56+w)*256 + c
__device__ __nv_bfloat16 g_wt[9 * 256 * 256];   // [rs][kout][c]

// ---------------- BFP quantization helper ----------------
__device__ __forceinline__ float bfp_apply(float v, float inv, float scale) {
    float r = rintf(v * inv);                 // round-half-even == jnp.round
    r = fminf(fmaxf(r, -128.0f), 127.0f);
    return r * scale;
}

// ---------------- quantize x (flat NCHW groups of 36) ----------------
__global__ void quant_x_kernel(const float* __restrict__ x) {
    int g = blockIdx.x * (blockDim.x >> 5) + (threadIdx.x >> 5);
    if (g >= NG_X) return;
    int lane = threadIdx.x & 31;
    long long base = (long long)g * 36;
    long long i1 = base + lane;
    long long i2 = base + 32 + lane;
    bool ok1 = (i1 < NE_X);
    bool ok2 = (lane < 4) && (i2 < NE_X);
    float v1 = ok1 ? x[i1] : 0.0f;
    float v2 = ok2 ? x[i2] : 0.0f;
    float m = fmaxf(fabsf(v1), fabsf(v2));
    #pragma unroll
    for (int o = 16; o > 0; o >>= 1)
        m = fmaxf(m, __shfl_xor_sync(0xffffffffu, m, o));
    if (m > 0.0f) {
        int e;
        frexpf(m, &e);
        float scale = ldexpf(1.0f, e - 8);
        float inv   = ldexpf(1.0f, 8 - e);
        v1 = bfp_apply(v1, inv, scale);
        v2 = bfp_apply(v2, inv, scale);
    } else {
        v1 = 0.0f; v2 = 0.0f;
    }
    if (ok1) g_xq_nchw[i1] = __float2bfloat16(v1);
    if (ok2) g_xq_nchw[i2] = __float2bfloat16(v2);
}

// ---------------- transpose xq: NCHW -> NHWC ----------------
__global__ void transpose_x_kernel() {
    __shared__ __nv_bfloat16 t[32][33];
    int n   = blockIdx.z;
    int hw0 = blockIdx.y * 32;
    int c0  = blockIdx.x * 32;
    int tx = threadIdx.x & 31;
    int ty = threadIdx.x >> 5;
    const __nv_bfloat16* src = g_xq_nchw + (long long)n * CHW;
    #pragma unroll
    for (int i = 0; i < 4; ++i) {
        int c = c0 + ty + i * 8;
        t[ty + i * 8][tx] = src[(long long)c * HW + hw0 + tx];
    }
    __syncthreads();
    __nv_bfloat16* dst = g_xq + (long long)n * CHW;
    #pragma unroll
    for (int i = 0; i < 4; ++i) {
        int hw = hw0 + ty + i * 8;
        dst[(long long)hw * C_ + c0 + tx] = t[tx][ty + i * 8];
    }
}

// ---------------- quantize w + relayout [rs][kout][c] ----------------
__device__ __forceinline__ void store_w(int f, float q) {
    int kout = f / 2304;
    int rem  = f - kout * 2304;
    int c    = rem / 9;
    int rs   = rem - c * 9;
    g_wt[(rs * K_ + kout) * C_ + c] = __float2bfloat16(q);
}

__global__ void quant_w_kernel(const float* __restrict__ w) {
    int g = blockIdx.x * (blockDim.x >> 5) + (threadIdx.x >> 5);
    if (g >= NG_W) return;
    int lane = threadIdx.x & 31;
    int base = g * 36;
    int i1 = base + lane;
    int i2 = base + 32 + lane;
    float v1 = w[i1];
    float v2 = (lane < 4) ? w[i2] : 0.0f;
    float m = fmaxf(fabsf(v1), fabsf(v2));
    #pragma unroll
    for (int o = 16; o > 0; o >>= 1)
        m = fmaxf(m, __shfl_xor_sync(0xffffffffu, m, o));
    if (m > 0.0f) {
        int e;
        frexpf(m, &e);
        float scale = ldexpf(1.0f, e - 8);
        float inv   = ldexpf(1.0f, 8 - e);
        v1 = bfp_apply(v1, inv, scale);
        v2 = bfp_apply(v2, inv, scale);
    } else {
        v1 = 0.0f; v2 = 0.0f;
    }
    store_w(i1, v1);
    if (lane < 4) store_w(i2, v2);
}

// ---------------- MMA / async-copy primitives ----------------
__device__ __forceinline__ void mma16816(float* d, const uint32_t* a, const uint32_t* b) {
    asm volatile(
        "mma.sync.aligned.m16n8k16.row.col.f32.bf16.bf16.f32 "
        "{%0,%1,%2,%3}, {%4,%5,%6,%7}, {%8,%9}, {%0,%1,%2,%3};\n"
        : "+f"(d[0]), "+f"(d[1]), "+f"(d[2]), "+f"(d[3])
        : "r"(a[0]), "r"(a[1]), "r"(a[2]), "r"(a[3]),
          "r"(b[0]), "r"(b[1]));
}

__device__ __forceinline__ void ldsm_x4(uint32_t* r, uint32_t addr) {
    asm volatile("ldmatrix.sync.aligned.m8n8.x4.shared.b16 {%0,%1,%2,%3}, [%4];\n"
                 : "=r"(r[0]), "=r"(r[1]), "=r"(r[2]), "=r"(r[3]) : "r"(addr));
}

__device__ __forceinline__ void cp_async16(uint32_t saddr, const void* g, int src_sz) {
    asm volatile("cp.async.ca.shared.global [%0], [%1], 16, %2;\n"
                 :: "r"(saddr), "l"(g), "r"(src_sz));
}
__device__ __forceinline__ void cp_commit() {
    asm volatile("cp.async.commit_group;\n");
}
__device__ __forceinline__ void cp_wait1() {
    asm volatile("cp.async.wait_group 1;\n");
}

// ---------------- bf16 HMMA implicit-GEMM conv, cp.async double-buffered ----------------
// Dynamic smem layout (halves): As[2][128*64] at 0, Bs[2][128*64] at 32768 bytes.
// Smem layout per tile row: 64 halves = 8 x 16B units; 16B unit c stored at c^(row&7).
static constexpr int STAGE_BYTES = 128 * 64 * 2;   // 16384
static constexpr int CONV_SMEM   = 4 * STAGE_BYTES; // 65536

__global__ void __launch_bounds__(256, 2)
conv_kernel(const float* __restrict__ bias, float* __restrict__ out) {
    extern __shared__ __align__(16) __nv_bfloat16 smem[];
    __shared__ int s_n[128], s_pix[128];

    const int tid = threadIdx.x;
    const int m0  = blockIdx.y * 128;
    const int bn  = blockIdx.x;

    if (tid < 128) {
        int m  = m0 + tid;
        int nn = m / HW;
        s_n[tid]   = nn;
        s_pix[tid] = m - nn * HW;
    }

    // ---- load-thread metadata: thread covers rows (tid>>3)+32p, 16B col tid&7 ----
    const int lc = tid & 7;          // 16B column unit
    const int lr = tid >> 3;         // base row (0..31)
    const int swz = lc ^ (lr & 7);   // swizzled 16B unit (row&7 invariant across passes)
    int am[4], ap[4], aq[4];
    #pragma unroll
    for (int p = 0; p < 4; ++p) {
        int m  = m0 + lr + 32 * p;
        int nn = m / HW;
        int rem = m - nn * HW;
        int hh = rem / W_;
        ap[p] = hh;
        aq[p] = rem - hh * W_;
        am[p] = m;
    }

    const uint32_t smem_u = (uint32_t)__cvta_generic_to_shared(smem);
    // cp.async destination byte offsets (stage-relative), constant per thread
    const uint32_t dst_off = (uint32_t)(lr * 128 + swz * 16);

    // ---- MMA fragment addressing (lane-constant parts) ----
    const int lane = tid & 31, warp = tid >> 5;
    const int wm = warp & 1;         // 2 warps along M (64 rows)
    const int wn = warp >> 1;        // 4 warps along N (32 cols)
    const int l7 = lane & 7;
    uint32_t a_row_b[4], b_row_b[2];
    #pragma unroll
    for (int i = 0; i < 4; ++i)
        a_row_b[i] = (uint32_t)((wm * 64 + i * 16 + (lane & 15)) * 128);
    #pragma unroll
    for (int jj = 0; jj < 2; ++jj)
        b_row_b[jj] = (uint32_t)((wn * 32 + jj * 16 + l7 + ((lane >> 4) << 3)) * 128);
    const int a_chi = lane >> 4;         // col-unit add for A ldmatrix
    const int b_chi = (lane >> 3) & 1;   // col-unit add for B ldmatrix

    float acc[4][4][4];
    #pragma unroll
    for (int i = 0; i < 4; ++i)
        #pragma unroll
        for (int j = 0; j < 4; ++j)
            #pragma unroll
            for (int k = 0; k < 4; ++k) acc[i][j][k] = 0.0f;

    // ---- stage loader: kt = cb*9 + rs; channels cb*64..+63, tap rs ----
    auto load_stage = [&](int kt, int buf) {
        int cb = kt / 9;
        int rs = kt - cb * 9;
        int r  = rs / 3;
        int s  = rs - r * 3;
        int doff  = (r - 1) * 56 + (s - 1);
        int cbase = cb * 64;
        uint32_t adst = smem_u + (uint32_t)buf * STAGE_BYTES + dst_off;
        uint32_t bdst = adst + 2u * STAGE_BYTES;
        #pragma unroll
        for (int p = 0; p < 4; ++p) {
            int h = ap[p] + r - 1;
            int w = aq[p] + s - 1;
            bool ok = ((unsigned)h < 56u) && ((unsigned)w < 56u);
            long long off = ok ? ((long long)(am[p] + doff) * C_ + cbase + lc * 8) : 0ll;
            cp_async16(adst + (uint32_t)(p * 32 * 128), g_xq + off, ok ? 16 : 0);
        }
        #pragma unroll
        for (int p = 0; p < 4; ++p) {
            int kout = lr + 32 * p;
            const __nv_bfloat16* src =
                g_wt + ((rs * K_ + bn * 128 + kout) * C_ + cbase + lc * 8);
            cp_async16(bdst + (uint32_t)(p * 32 * 128), src, 16);
        }
    };

    // ---- prologue ----
    load_stage(0, 0);
    cp_commit();

    // ---- mainloop: 36 k-steps of BK=64 ----
    for (int kt = 0; kt < 36; ++kt) {
        if (kt < 35) load_stage(kt + 1, (kt + 1) & 1);
        cp_commit();
        cp_wait1();
        __syncthreads();

        const uint32_t Ab = smem_u + (uint32_t)(kt & 1) * STAGE_BYTES;
        const uint32_t Bb = Ab + 2u * STAGE_BYTES;

        #pragma unroll
        for (int kku = 0; kku < 4; ++kku) {          // kk = kku*16 halves
            const int cu = kku * 2;                   // 16B col unit of kk
            uint32_t a[4][4], b[2][4];
            #pragma unroll
            for (int i = 0; i < 4; ++i)
                ldsm_x4(a[i], Ab + a_row_b[i] + (uint32_t)(((cu + a_chi) ^ l7) * 16));
            #pragma unroll
            for (int jj = 0; jj < 2; ++jj)
                ldsm_x4(b[jj], Bb + b_row_b[jj] + (uint32_t)(((cu + b_chi) ^ l7) * 16));
            #pragma unroll
            for (int i = 0; i < 4; ++i) {
                #pragma unroll
                for (int j = 0; j < 4; ++j)
                    mma16816(acc[i][j], a[i], &b[j >> 1][(j & 1) * 2]);
            }
        }
        __syncthreads();
    }

    // ---- epilogue ----
    const int gi = lane >> 2, ti = lane & 3;
    #pragma unroll
    for (int i = 0; i < 4; ++i) {
        int rl0 = wm * 64 + i * 16 + gi;
        int rl1 = rl0 + 8;
        int o0 = s_n[rl0] * CHW + s_pix[rl0];
        int o1 = s_n[rl1] * CHW + s_pix[rl1];
        #pragma unroll
        for (int j = 0; j < 4; ++j) {
            int kout = bn * 128 + wn * 32 + j * 8 + ti * 2;
            float b0 = bias[kout];
            float b1 = bias[kout + 1];
            out[o0 + kout * HW]       = acc[i][j][0] + b0;
            out[o0 + (kout + 1) * HW] = acc[i][j][1] + b1;
            out[o1 + kout * HW]       = acc[i][j][2] + b0;
            out[o1 + (kout + 1) * HW] = acc[i][j][3] + b1;
        }
    }
}

// ---------------- launch ----------------
extern "C" void kernel_launch(void* const* d_in, const int* in_sizes, int n_in,
                              void* d_out, int out_size) {
    const float* x    = (const float*)d_in[0];
    const float* w    = (const float*)d_in[1];
    const float* bias = (const float*)d_in[2];
    float* out = (float*)d_out;

    cudaFuncSetAttribute(conv_kernel, cudaFuncAttributeMaxDynamicSharedMemorySize, CONV_SMEM);

    quant_x_kernel<<<(NG_X + 7) / 8, 256>>>(x);
    quant_w_kernel<<<(NG_W + 7) / 8, 256>>>(w);
    {
        dim3 g(8, 98, 16);
        transpose_x_kernel<<<g, 256>>>();
    }
    {
        dim3 g(2, MGEMM / 128);
        conv_kernel<<<g, 256, CONV_SMEM>>>(bias, out);
    }
}

// round 4
// speedup vs baseline: 1.4519x; 1.0569x over previous
#include <cuda_runtime.h>
#include <cuda_bf16.h>
#include <cstdint>

// ---------------- problem constants ----------------
static constexpr int N_  = 16;
static constexpr int C_  = 256;
static constexpr int H_  = 56;
static constexpr int W_  = 56;
static constexpr int K_  = 256;
static constexpr int HW  = H_ * W_;          // 3136
static constexpr int CHW = C_ * HW;          // 802816
static constexpr long long NE_X = (long long)N_ * CHW;   // 12,845,056
static constexpr int NE_W = K_ * C_ * 9;     // 589,824
static constexpr int NG_X = (int)((NE_X + 35) / 36);     // 356,808
static constexpr int NG_W = NE_W / 36;       // 16,384
static constexpr int MGEMM = N_ * HW;        // 50,176 = 392*128

// ---------------- device scratch ----------------
__device__ __nv_bfloat16 g_xq_nchw[12845056];
__device__ __nv_bfloat16 g_xq[12845056];        // NHWC
__device__ __nv_bfloat16 g_wt[9 * 256 * 256];   // [rs][kout][c]

// ---------------- BFP quantization ----------------
__device__ __forceinline__ float bfp_apply(float v, float inv, float scale) {
    float r = rintf(v * inv);                 // round-half-even == jnp.round
    r = fminf(fmaxf(r, -128.0f), 127.0f);
    return r * scale;
}

__global__ void quant_x_kernel(const float* __restrict__ x) {
    int g = blockIdx.x * (blockDim.x >> 5) + (threadIdx.x >> 5);
    if (g >= NG_X) return;
    int lane = threadIdx.x & 31;
    long long base = (long long)g * 36;
    long long i1 = base + lane;
    long long i2 = base + 32 + lane;
    bool ok1 = (i1 < NE_X);
    bool ok2 = (lane < 4) && (i2 < NE_X);
    float v1 = ok1 ? x[i1] : 0.0f;
    float v2 = ok2 ? x[i2] : 0.0f;
    float m = fmaxf(fabsf(v1), fabsf(v2));
    #pragma unroll
    for (int o = 16; o > 0; o >>= 1)
        m = fmaxf(m, __shfl_xor_sync(0xffffffffu, m, o));
    if (m > 0.0f) {
        int e;
        frexpf(m, &e);
        float scale = ldexpf(1.0f, e - 8);
        float inv   = ldexpf(1.0f, 8 - e);
        v1 = bfp_apply(v1, inv, scale);
        v2 = bfp_apply(v2, inv, scale);
    } else { v1 = 0.0f; v2 = 0.0f; }
    if (ok1) g_xq_nchw[i1] = __float2bfloat16(v1);
    if (ok2) g_xq_nchw[i2] = __float2bfloat16(v2);
}

__global__ void transpose_x_kernel() {
    __shared__ __nv_bfloat16 t[32][33];
    int n   = blockIdx.z;
    int hw0 = blockIdx.y * 32;
    int c0  = blockIdx.x * 32;
    int tx = threadIdx.x & 31;
    int ty = threadIdx.x >> 5;
    const __nv_bfloat16* src = g_xq_nchw + (long long)n * CHW;
    #pragma unroll
    for (int i = 0; i < 4; ++i)
        t[ty + i * 8][tx] = src[(long long)(c0 + ty + i * 8) * HW + hw0 + tx];
    __syncthreads();
    __nv_bfloat16* dst = g_xq + (long long)n * CHW;
    #pragma unroll
    for (int i = 0; i < 4; ++i)
        dst[(long long)(hw0 + ty + i * 8) * C_ + c0 + tx] = t[tx][ty + i * 8];
}

__device__ __forceinline__ void store_w(int f, float q) {
    int kout = f / 2304;
    int rem  = f - kout * 2304;
    int c    = rem / 9;
    int rs   = rem - c * 9;
    g_wt[(rs * K_ + kout) * C_ + c] = __float2bfloat16(q);
}

__global__ void quant_w_kernel(const float* __restrict__ w) {
    int g = blockIdx.x * (blockDim.x >> 5) + (threadIdx.x >> 5);
    if (g >= NG_W) return;
    int lane = threadIdx.x & 31;
    int base = g * 36;
    int i1 = base + lane;
    int i2 = base + 32 + lane;
    float v1 = w[i1];
    float v2 = (lane < 4) ? w[i2] : 0.0f;
    float m = fmaxf(fabsf(v1), fabsf(v2));
    #pragma unroll
    for (int o = 16; o > 0; o >>= 1)
        m = fmaxf(m, __shfl_xor_sync(0xffffffffu, m, o));
    if (m > 0.0f) {
        int e;
        frexpf(m, &e);
        float scale = ldexpf(1.0f, e - 8);
        float inv   = ldexpf(1.0f, 8 - e);
        v1 = bfp_apply(v1, inv, scale);
        v2 = bfp_apply(v2, inv, scale);
    } else { v1 = 0.0f; v2 = 0.0f; }
    store_w(i1, v1);
    if (lane < 4) store_w(i2, v2);
}

// ---------------- MMA / async-copy primitives ----------------
__device__ __forceinline__ void mma16816(float* d, const uint32_t* a, const uint32_t* b) {
    asm volatile(
        "mma.sync.aligned.m16n8k16.row.col.f32.bf16.bf16.f32 "
        "{%0,%1,%2,%3}, {%4,%5,%6,%7}, {%8,%9}, {%0,%1,%2,%3};\n"
        : "+f"(d[0]), "+f"(d[1]), "+f"(d[2]), "+f"(d[3])
        : "r"(a[0]), "r"(a[1]), "r"(a[2]), "r"(a[3]),
          "r"(b[0]), "r"(b[1]));
}

__device__ __forceinline__ void ldsm_x4(uint32_t* r, uint32_t addr) {
    asm volatile("ldmatrix.sync.aligned.m8n8.x4.shared.b16 {%0,%1,%2,%3}, [%4];\n"
                 : "=r"(r[0]), "=r"(r[1]), "=r"(r[2]), "=r"(r[3]) : "r"(addr));
}

__device__ __forceinline__ void cp_async16(uint32_t saddr, const void* g, int src_sz) {
    asm volatile("cp.async.cg.shared.global [%0], [%1], 16, %2;\n"
                 :: "r"(saddr), "l"(g), "r"(src_sz));
}
__device__ __forceinline__ void cp_commit() { asm volatile("cp.async.commit_group;\n"); }
__device__ __forceinline__ void cp_wait1()  { asm volatile("cp.async.wait_group 1;\n"); }

// ---------------- conv: 3-stage cp.async + HMMA ----------------
static constexpr int TILE_B    = 128 * 64 * 2;    // 16 KB per A or B tile (BK=64 bf16)
static constexpr int STAGE_B   = 2 * TILE_B;      // 32 KB
static constexpr int CONV_SMEM = 3 * STAGE_B + 1024;

__global__ void __launch_bounds__(256, 2)
conv_kernel(const float* __restrict__ bias, float* __restrict__ out) {
    extern __shared__ char dsm_raw[];
    __shared__ int s_n[128], s_pix[128];

    const int tid = threadIdx.x;
    const int m0  = blockIdx.y * 128;
    const int bn  = blockIdx.x;

    const uint32_t dsm_u =
        ((uint32_t)__cvta_generic_to_shared(dsm_raw) + 1023u) & ~1023u;

    if (tid < 128) {
        int m  = m0 + tid;
        int nn = m / HW;
        s_n[tid]   = nn;
        s_pix[tid] = m - nn * HW;
    }

    // ---- loader metadata: row lr(+32p), 16B unit lc, XOR-swizzled dst ----
    const int lc = tid & 7;
    const int lr = tid >> 3;
    const uint32_t dst_off = (uint32_t)(lr * 128 + (lc ^ (lr & 7)) * 16);
    int am[4], ap[4], aq[4];
    #pragma unroll
    for (int p = 0; p < 4; ++p) {
        int m  = m0 + lr + 32 * p;
        int nn = m / HW;
        int rem = m - nn * HW;
        int hh = rem / W_;
        ap[p] = hh;
        aq[p] = rem - hh * W_;
        am[p] = m;
    }

    // ---- MMA fragment addressing (R2-proven) ----
    const int lane = tid & 31, warp = tid >> 5;
    const int wm = warp & 1;
    const int wn = warp >> 1;
    const int l7 = lane & 7;
    uint32_t a_row_b[4], b_row_b[2];
    #pragma unroll
    for (int i = 0; i < 4; ++i)
        a_row_b[i] = (uint32_t)((wm * 64 + i * 16 + (lane & 15)) * 128);
    #pragma unroll
    for (int jj = 0; jj < 2; ++jj)
        b_row_b[jj] = (uint32_t)((wn * 32 + jj * 16 + l7 + ((lane >> 4) << 3)) * 128);
    const int a_chi = lane >> 4;
    const int b_chi = (lane >> 3) & 1;

    float acc[4][4][4];
    #pragma unroll
    for (int i = 0; i < 4; ++i)
        #pragma unroll
        for (int j = 0; j < 4; ++j)
            #pragma unroll
            for (int k = 0; k < 4; ++k) acc[i][j][k] = 0.0f;

    auto load_stage = [&](int kt, int buf) {
        int cb = kt / 9;
        int rs = kt - cb * 9;
        int r  = rs / 3;
        int s  = rs - r * 3;
        int doff  = (r - 1) * 56 + (s - 1);
        int cbase = cb * 64;
        uint32_t adst = dsm_u + (uint32_t)buf * STAGE_B + dst_off;
        uint32_t bdst = adst + (uint32_t)TILE_B;
        #pragma unroll
        for (int p = 0; p < 4; ++p) {
            int h = ap[p] + r - 1;
            int w = aq[p] + s - 1;
            bool ok = ((unsigned)h < 56u) && ((unsigned)w < 56u);
            long long off = ok ? ((long long)(am[p] + doff) * C_ + cbase + lc * 8) : 0ll;
            cp_async16(adst + (uint32_t)(p * 32 * 128), g_xq + off, ok ? 16 : 0);
        }
        #pragma unroll
        for (int p = 0; p < 4; ++p) {
            int kout = lr + 32 * p;
            cp_async16(bdst + (uint32_t)(p * 32 * 128),
                       g_wt + ((rs * K_ + bn * 128 + kout) * C_ + cbase + lc * 8), 16);
        }
    };

    __syncthreads();            // s_n/s_pix visible; also before smem reuse

    // ---- prologue: stages 0,1 in flight ----
    load_stage(0, 0); cp_commit();
    load_stage(1, 1); cp_commit();

    // ---- mainloop: 36 k-steps of BK=64, one barrier each ----
    int buf_cur = 0;
    for (int kt = 0; kt < 36; ++kt) {
        cp_wait1();                     // stage kt landed (newest group may pend)
        __syncthreads();                // publish stage kt; close reads of kt-1

        // issue loads for stage kt+2 into buffer consumed at kt-1
        int buf_load = buf_cur + 2; if (buf_load >= 3) buf_load -= 3;
        if (kt + 2 < 36) load_stage(kt + 2, buf_load);
        cp_commit();                    // exactly one group per iteration

        const uint32_t Ab = dsm_u + (uint32_t)buf_cur * STAGE_B;
        const uint32_t Bb = Ab + (uint32_t)TILE_B;

        #pragma unroll
        for (int kku = 0; kku < 4; ++kku) {
            const int cu = kku * 2;
            uint32_t a[4][4], b[2][4];
            #pragma unroll
            for (int i = 0; i < 4; ++i)
                ldsm_x4(a[i], Ab + a_row_b[i] + (uint32_t)(((cu + a_chi) ^ l7) * 16));
            #pragma unroll
            for (int jj = 0; jj < 2; ++jj)
                ldsm_x4(b[jj], Bb + b_row_b[jj] + (uint32_t)(((cu + b_chi) ^ l7) * 16));
            #pragma unroll
            for (int i = 0; i < 4; ++i)
                #pragma unroll
                for (int j = 0; j < 4; ++j)
                    mma16816(acc[i][j], a[i], &b[j >> 1][(j & 1) * 2]);
        }
        if (++buf_cur == 3) buf_cur = 0;
    }

    // ---- epilogue ----
    const int gi = lane >> 2, ti = lane & 3;
    #pragma unroll
    for (int i = 0; i < 4; ++i) {
        int rl0 = wm * 64 + i * 16 + gi;
        int rl1 = rl0 + 8;
        int o0 = s_n[rl0] * CHW + s_pix[rl0];
        int o1 = s_n[rl1] * CHW + s_pix[rl1];
        #pragma unroll
        for (int j = 0; j < 4; ++j) {
            int kout = bn * 128 + wn * 32 + j * 8 + ti * 2;
            float b0 = bias[kout];
            float b1 = bias[kout + 1];
            out[o0 + kout * HW]       = acc[i][j][0] + b0;
            out[o0 + (kout + 1) * HW] = acc[i][j][1] + b1;
            out[o1 + kout * HW]       = acc[i][j][2] + b0;
            out[o1 + (kout + 1) * HW] = acc[i][j][3] + b1;
        }
    }
}

// ---------------- launch ----------------
extern "C" void kernel_launch(void* const* d_in, const int* in_sizes, int n_in,
                              void* d_out, int out_size) {
    const float* x    = (const float*)d_in[0];
    const float* w    = (const float*)d_in[1];
    const float* bias = (const float*)d_in[2];
    float* out = (float*)d_out;

    cudaFuncSetAttribute(conv_kernel, cudaFuncAttributeMaxDynamicSharedMemorySize, CONV_SMEM);

    quant_x_kernel<<<(NG_X + 7) / 8, 256>>>(x);
    quant_w_kernel<<<(NG_W + 7) / 8, 256>>>(w);
    {
        dim3 g(8, 98, 16);
        transpose_x_kernel<<<g, 256>>>();
    }
    {
        dim3 g(2, MGEMM / 128);
        conv_kernel<<<g, 256, CONV_SMEM>>>(bias, out);
    }
}

// round 5
// speedup vs baseline: 1.7743x; 1.2221x over previous
#include <cuda_runtime.h>
#include <cuda_bf16.h>
#include <cstdint>

// ---------------- problem constants ----------------
static constexpr int N_  = 16;
static constexpr int C_  = 256;
static constexpr int H_  = 56;
static constexpr int W_  = 56;
static constexpr int K_  = 256;
static constexpr int HW  = H_ * W_;          // 3136
static constexpr int CHW = C_ * HW;          // 802816
static constexpr long long NE_X = (long long)N_ * CHW;   // 12,845,056
static constexpr int NE_W = K_ * C_ * 9;     // 589,824
static constexpr int NG_W = NE_W / 36;       // 16,384
static constexpr int MGEMM = N_ * HW;        // 50,176 = 392*128

// ---------------- device scratch ----------------
__device__ __nv_bfloat16 g_xq_nchw[12845056];
__device__ __nv_bfloat16 g_xq[12845056];        // NHWC
__device__ __nv_bfloat16 g_wt[9 * 256 * 256];   // [rs][kout][c]

// ---------------- BFP quantization ----------------
__device__ __forceinline__ float bfp_apply(float v, float inv, float scale) {
    float r = rintf(v * inv);                 // round-half-even == jnp.round
    r = fminf(fmaxf(r, -128.0f), 127.0f);
    return r * scale;
}

// ---------------- quantize x: block-staged, 128 groups (4608 floats) per block ----
static constexpr int QX_GROUPS = 128;
static constexpr int QX_ELEMS  = QX_GROUPS * 36;          // 4608
static constexpr long long NE_X4 = NE_X / 4;              // 3,211,264 float4 (exact)

__global__ void __launch_bounds__(128)
quant_x_kernel(const float* __restrict__ x) {
    __shared__ float s[QX_ELEMS];                         // 18 KB
    __shared__ __nv_bfloat16 q[QX_ELEMS];                 // 9 KB
    const int tid = threadIdx.x;
    const long long b4 = (long long)blockIdx.x * (QX_ELEMS / 4);   // float4 base

    // phase 1: coalesced float4 loads -> smem
    const float4* x4 = (const float4*)x;
    float4* s4 = (float4*)s;
    #pragma unroll
    for (int k = 0; k < 9; ++k) {
        long long f = b4 + tid + k * 128;
        float4 v = (f < NE_X4) ? x4[f] : make_float4(0.f, 0.f, 0.f, 0.f);
        s4[tid + k * 128] = v;
    }
    __syncthreads();

    // phase 2: thread-per-group max + quantize
    {
        const float* sg = s + tid * 36;
        float m = 0.0f;
        #pragma unroll
        for (int j = 0; j < 36; ++j) m = fmaxf(m, fabsf(sg[j]));
        __nv_bfloat16* qg = q + tid * 36;
        if (m > 0.0f) {
            int e;
            frexpf(m, &e);
            float scale = ldexpf(1.0f, e - 8);
            float inv   = ldexpf(1.0f, 8 - e);
            #pragma unroll
            for (int j = 0; j < 36; ++j)
                qg[j] = __float2bfloat16(bfp_apply(sg[j], inv, scale));
        } else {
            #pragma unroll
            for (int j = 0; j < 36; ++j) qg[j] = __float2bfloat16(0.0f);
        }
    }
    __syncthreads();

    // phase 3: coalesced uint2 (4 halves) stores
    const uint2* q2 = (const uint2*)q;
    uint2* o2 = (uint2*)g_xq_nchw;
    const long long ob = (long long)blockIdx.x * (QX_ELEMS / 4);
    #pragma unroll
    for (int k = 0; k < 9; ++k) {
        long long go = ob + tid + k * 128;
        if (go < NE_X4) o2[go] = q2[tid + k * 128];
    }
}

// ---------------- transpose xq: NCHW -> NHWC (uint32 2x2 micro-transpose) ------
// tile: 32 channels x 64 hw (= 32x32 uint32 on src side)
__global__ void __launch_bounds__(256)
transpose_x_kernel() {
    __shared__ uint32_t t[32][33];
    const int tid  = threadIdx.x;
    const int hwp0 = blockIdx.x * 32;     // uint32 (=2 hw) tile base: 1568/32 = 49
    const int c0   = blockIdx.y * 32;     // 256/32 = 8
    const int n    = blockIdx.z;

    const uint32_t* src = (const uint32_t*)(g_xq_nchw + (long long)n * CHW);
    // load: 32 rows (c) x 32 uint32 (hw pairs)
    #pragma unroll
    for (int p = 0; p < 4; ++p) {
        int cl  = p * 8 + (tid >> 5);
        int hwl = tid & 31;
        t[cl][hwl] = src[(long long)(c0 + cl) * (HW / 2) + hwp0 + hwl];
    }
    __syncthreads();

    // store: 64 hw rows x 16 uint32 (c pairs)
    uint32_t* dst = (uint32_t*)(g_xq + (long long)n * CHW);
    const int cp = tid & 15;              // c-pair 0..15
    #pragma unroll
    for (int qq = 0; qq < 4; ++qq) {
        int hwl = (tid >> 4) + qq * 16;   // 0..63
        uint32_t u0 = t[2 * cp][hwl >> 1];
        uint32_t u1 = t[2 * cp + 1][hwl >> 1];
        uint32_t d = (hwl & 1) ? __byte_perm(u0, u1, 0x7632)
                               : __byte_perm(u0, u1, 0x5410);
        dst[(long long)(hwp0 * 2 + hwl) * (C_ / 2) + (c0 >> 1) + cp] = d;
    }
}

// ---------------- quantize w + relayout [rs][kout][c] ----------------
__device__ __forceinline__ void store_w(int f, float q) {
    int kout = f / 2304;
    int rem  = f - kout * 2304;
    int c    = rem / 9;
    int rs   = rem - c * 9;
    g_wt[(rs * K_ + kout) * C_ + c] = __float2bfloat16(q);
}

__global__ void quant_w_kernel(const float* __restrict__ w) {
    int g = blockIdx.x * (blockDim.x >> 5) + (threadIdx.x >> 5);
    if (g >= NG_W) return;
    int lane = threadIdx.x & 31;
    int base = g * 36;
    int i1 = base + lane;
    int i2 = base + 32 + lane;
    float v1 = w[i1];
    float v2 = (lane < 4) ? w[i2] : 0.0f;
    float m = fmaxf(fabsf(v1), fabsf(v2));
    #pragma unroll
    for (int o = 16; o > 0; o >>= 1)
        m = fmaxf(m, __shfl_xor_sync(0xffffffffu, m, o));
    if (m > 0.0f) {
        int e;
        frexpf(m, &e);
        float scale = ldexpf(1.0f, e - 8);
        float inv   = ldexpf(1.0f, 8 - e);
        v1 = bfp_apply(v1, inv, scale);
        v2 = bfp_apply(v2, inv, scale);
    } else { v1 = 0.0f; v2 = 0.0f; }
    store_w(i1, v1);
    if (lane < 4) store_w(i2, v2);
}

// ---------------- MMA / async-copy primitives ----------------
__device__ __forceinline__ void mma16816(float* d, const uint32_t* a, const uint32_t* b) {
    asm volatile(
        "mma.sync.aligned.m16n8k16.row.col.f32.bf16.bf16.f32 "
        "{%0,%1,%2,%3}, {%4,%5,%6,%7}, {%8,%9}, {%0,%1,%2,%3};\n"
        : "+f"(d[0]), "+f"(d[1]), "+f"(d[2]), "+f"(d[3])
        : "r"(a[0]), "r"(a[1]), "r"(a[2]), "r"(a[3]),
          "r"(b[0]), "r"(b[1]));
}

__device__ __forceinline__ void ldsm_x4(uint32_t* r, uint32_t addr) {
    asm volatile("ldmatrix.sync.aligned.m8n8.x4.shared.b16 {%0,%1,%2,%3}, [%4];\n"
                 : "=r"(r[0]), "=r"(r[1]), "=r"(r[2]), "=r"(r[3]) : "r"(addr));
}

__device__ __forceinline__ void cp_async16(uint32_t saddr, const void* g, int src_sz) {
    asm volatile("cp.async.cg.shared.global [%0], [%1], 16, %2;\n"
                 :: "r"(saddr), "l"(g), "r"(src_sz));
}
__device__ __forceinline__ void cp_commit() { asm volatile("cp.async.commit_group;\n"); }
__device__ __forceinline__ void cp_wait1()  { asm volatile("cp.async.wait_group 1;\n"); }

// ---------------- conv: 3-stage cp.async + HMMA ----------------
static constexpr int TILE_B    = 128 * 64 * 2;    // 16 KB per A or B tile (BK=64 bf16)
static constexpr int STAGE_B   = 2 * TILE_B;      // 32 KB
static constexpr int CONV_SMEM = 3 * STAGE_B + 1024;

__global__ void __launch_bounds__(256, 2)
conv_kernel(const float* __restrict__ bias, float* __restrict__ out) {
    extern __shared__ char dsm_raw[];
    __shared__ int s_n[128], s_pix[128];

    const int tid = threadIdx.x;
    const int m0  = blockIdx.y * 128;
    const int bn  = blockIdx.x;

    const uint32_t dsm_u =
        ((uint32_t)__cvta_generic_to_shared(dsm_raw) + 1023u) & ~1023u;

    if (tid < 128) {
        int m  = m0 + tid;
        int nn = m / HW;
        s_n[tid]   = nn;
        s_pix[tid] = m - nn * HW;
    }

    // ---- loader metadata ----
    const int lc = tid & 7;
    const int lr = tid >> 3;
    const uint32_t dst_off = (uint32_t)(lr * 128 + (lc ^ (lr & 7)) * 16);
    int am[4], ap[4], aq[4];
    #pragma unroll
    for (int p = 0; p < 4; ++p) {
        int m  = m0 + lr + 32 * p;
        int nn = m / HW;
        int rem = m - nn * HW;
        int hh = rem / W_;
        ap[p] = hh;
        aq[p] = rem - hh * W_;
        am[p] = m;
    }

    // ---- MMA fragment addressing ----
    const int lane = tid & 31, warp = tid >> 5;
    const int wm = warp & 1;
    const int wn = warp >> 1;
    const int l7 = lane & 7;
    uint32_t a_row_b[4], b_row_b[2];
    #pragma unroll
    for (int i = 0; i < 4; ++i)
        a_row_b[i] = (uint32_t)((wm * 64 + i * 16 + (lane & 15)) * 128);
    #pragma unroll
    for (int jj = 0; jj < 2; ++jj)
        b_row_b[jj] = (uint32_t)((wn * 32 + jj * 16 + l7 + ((lane >> 4) << 3)) * 128);
    const int a_chi = lane >> 4;
    const int b_chi = (lane >> 3) & 1;

    float acc[4][4][4];
    #pragma unroll
    for (int i = 0; i < 4; ++i)
        #pragma unroll
        for (int j = 0; j < 4; ++j)
            #pragma unroll
            for (int k = 0; k < 4; ++k) acc[i][j][k] = 0.0f;

    auto load_stage = [&](int kt, int buf) {
        int cb = kt / 9;
        int rs = kt - cb * 9;
        int r  = rs / 3;
        int s  = rs - r * 3;
        int doff  = (r - 1) * 56 + (s - 1);
        int cbase = cb * 64;
        uint32_t adst = dsm_u + (uint32_t)buf * STAGE_B + dst_off;
        uint32_t bdst = adst + (uint32_t)TILE_B;
        #pragma unroll
        for (int p = 0; p < 4; ++p) {
            int h = ap[p] + r - 1;
            int w = aq[p] + s - 1;
            bool ok = ((unsigned)h < 56u) && ((unsigned)w < 56u);
            long long off = ok ? ((long long)(am[p] + doff) * C_ + cbase + lc * 8) : 0ll;
            cp_async16(adst + (uint32_t)(p * 32 * 128), g_xq + off, ok ? 16 : 0);
        }
        #pragma unroll
        for (int p = 0; p < 4; ++p) {
            int kout = lr + 32 * p;
            cp_async16(bdst + (uint32_t)(p * 32 * 128),
                       g_wt + ((rs * K_ + bn * 128 + kout) * C_ + cbase + lc * 8), 16);
        }
    };

    // one k-step: consume buffer `buf` (compile-time), prefetch kt+2 into `bufl`
    auto kstep = [&](int kt, int buf, int bufl) {
        cp_wait1();
        __syncthreads();
        if (kt + 2 < 36) load_stage(kt + 2, bufl);
        cp_commit();

        const uint32_t Ab = dsm_u + (uint32_t)buf * STAGE_B;
        const uint32_t Bb = Ab + (uint32_t)TILE_B;
        #pragma unroll
        for (int kku = 0; kku < 4; ++kku) {
            const int cu = kku * 2;
            uint32_t a[4][4], b[2][4];
            #pragma unroll
            for (int i = 0; i < 4; ++i)
                ldsm_x4(a[i], Ab + a_row_b[i] + (uint32_t)(((cu + a_chi) ^ l7) * 16));
            #pragma unroll
            for (int jj = 0; jj < 2; ++jj)
                ldsm_x4(b[jj], Bb + b_row_b[jj] + (uint32_t)(((cu + b_chi) ^ l7) * 16));
            #pragma unroll
            for (int i = 0; i < 4; ++i)
                #pragma unroll
                for (int j = 0; j < 4; ++j)
                    mma16816(acc[i][j], a[i], &b[j >> 1][(j & 1) * 2]);
        }
    };

    __syncthreads();
    load_stage(0, 0); cp_commit();
    load_stage(1, 1); cp_commit();

    for (int kt = 0; kt < 36; kt += 3) {   // ring indices compile-time
        kstep(kt + 0, 0, 2);
        kstep(kt + 1, 1, 0);
        kstep(kt + 2, 2, 1);
    }

    // ---- epilogue ----
    const int gi = lane >> 2, ti = lane & 3;
    #pragma unroll
    for (int i = 0; i < 4; ++i) {
        int rl0 = wm * 64 + i * 16 + gi;
        int rl1 = rl0 + 8;
        int o0 = s_n[rl0] * CHW + s_pix[rl0];
        int o1 = s_n[rl1] * CHW + s_pix[rl1];
        #pragma unroll
        for (int j = 0; j < 4; ++j) {
            int kout = bn * 128 + wn * 32 + j * 8 + ti * 2;
            float b0 = bias[kout];
            float b1 = bias[kout + 1];
            out[o0 + kout * HW]       = acc[i][j][0] + b0;
            out[o0 + (kout + 1) * HW] = acc[i][j][1] + b1;
            out[o1 + kout * HW]       = acc[i][j][2] + b0;
            out[o1 + (kout + 1) * HW] = acc[i][j][3] + b1;
        }
    }
}

// ---------------- launch ----------------
extern "C" void kernel_launch(void* const* d_in, const int* in_sizes, int n_in,
                              void* d_out, int out_size) {
    const float* x    = (const float*)d_in[0];
    const float* w    = (const float*)d_in[1];
    const float* bias = (const float*)d_in[2];
    float* out = (float*)d_out;

    cudaFuncSetAttribute(conv_kernel, cudaFuncAttributeMaxDynamicSharedMemorySize, CONV_SMEM);

    {
        int nblk = (int)((NE_X + QX_ELEMS - 1) / QX_ELEMS);   // 2788
        quant_x_kernel<<<nblk, 128>>>(x);
    }
    quant_w_kernel<<<(NG_W + 7) / 8, 256>>>(w);
    {
        dim3 g(49, 8, 16);
        transpose_x_kernel<<<g, 256>>>();
    }
    {
        dim3 g(2, MGEMM / 128);
        conv_kernel<<<g, 256, CONV_SMEM>>>(bias, out);
    }
}